// round 13
// baseline (speedup 1.0000x reference)
#include <cuda_runtime.h>
#include <cuda_fp16.h>
#include <cstdint>
#include <cstddef>

#define NN 50000
#define NE 800000

// ---------------- static scratch (no allocs allowed) ----------------
__device__ __half2 g_EP1[(size_t)NN * 64];    // [n][c] = (E,P) half2, c<64
__device__ float   g_aggr1[(size_t)NN * 64];
__device__ float   g_buf1[(size_t)NN * 256];  // h1 (normalized+relu)
__device__ __half2 g_EP2[(size_t)NN * 256];   // [n][c] c<256
__device__ float   g_aggr2[(size_t)NN * 256];
__device__ float   g_buf2[(size_t)NN * 128];  // h2
__device__ int     g_counts[NN];
__device__ int     g_off[NN + 1];
__device__ int     g_cur[NN];
__device__ int     g_srcs[NE];
__device__ int     g_bsum[64];
__device__ int     g_boff[64];
__device__ float   g_pool[4 * 128];

// transposed tf32-split weights: Wt[N][K], hi = tf32(W), lo = tf32(W - hi)
__device__ float g_WtP1h[64 * 64],   g_WtP1l[64 * 64];
__device__ float g_WtL1h[256 * 64],  g_WtL1l[256 * 64];
__device__ float g_WtR1h[256 * 64],  g_WtR1l[256 * 64];
__device__ float g_WtP2h[256 * 256], g_WtP2l[256 * 256];
__device__ float g_WtL2h[128 * 256], g_WtL2l[128 * 256];
__device__ float g_WtR2h[128 * 256], g_WtR2l[128 * 256];

// ---------------- helpers ----------------
__device__ __forceinline__ float tf32_rna(float x) {
    float r; asm("cvt.rna.tf32.f32 %0, %1;" : "=f"(r) : "f"(x)); return r;
}

// D_mma[16,8] += A_mma[16,8] * B_mma[8,8]; tf32 inputs (fp32 bit layout), fp32 acc.
__device__ __forceinline__ void mma8(float* c, const uint32_t* a, const uint32_t* b) {
    asm volatile(
        "mma.sync.aligned.m16n8k8.row.col.f32.tf32.tf32.f32 "
        "{%0,%1,%2,%3}, {%4,%5,%6,%7}, {%8,%9}, {%0,%1,%2,%3};"
        : "+f"(c[0]), "+f"(c[1]), "+f"(c[2]), "+f"(c[3])
        : "r"(a[0]), "r"(a[1]), "r"(a[2]), "r"(a[3]), "r"(b[0]), "r"(b[1]));
}

// ---------------- CSR build ----------------
__global__ void zero_k(int n) {
    int i = blockIdx.x * 256 + threadIdx.x;
    if (i < n) g_counts[i] = 0;
    if (i < 512) g_pool[i] = 0.0f;
}

__global__ void count_k(const int* __restrict__ ei, int E) {
    int i = blockIdx.x * 256 + threadIdx.x;
    if (i >= E) return;
    atomicAdd(&g_counts[ei[E + i]], 1);
}

__global__ void scan1_k(int n) {
    __shared__ int s[1024];
    int t = threadIdx.x;
    int i = blockIdx.x * 1024 + t;
    int v = (i < n) ? g_counts[i] : 0;
    s[t] = v;
    __syncthreads();
    for (int o = 1; o < 1024; o <<= 1) {
        int a = (t >= o) ? s[t - o] : 0;
        __syncthreads();
        s[t] += a;
        __syncthreads();
    }
    if (i < n) g_off[i + 1] = s[t];
    if (t == 1023) g_bsum[blockIdx.x] = s[1023];
}

__global__ void scan2_k(int nb) {
    __shared__ int s[64];
    int t = threadIdx.x;
    int v = (t < nb) ? g_bsum[t] : 0;
    s[t] = v;
    __syncthreads();
    for (int o = 1; o < 64; o <<= 1) {
        int a = (t >= o) ? s[t - o] : 0;
        __syncthreads();
        s[t] += a;
        __syncthreads();
    }
    if (t < nb) g_boff[t] = s[t] - v;
}

__global__ void scan3_k(int n) {
    int i = blockIdx.x * 256 + threadIdx.x;
    if (i >= n) return;
    int incl = g_off[i + 1] + g_boff[i >> 10];
    g_off[i + 1] = incl;
    if (i + 1 < n) g_cur[i + 1] = incl;
    if (i == 0) { g_off[0] = 0; g_cur[0] = 0; }
}

__global__ void scatter_k(const int* __restrict__ ei, int E) {
    int i = blockIdx.x * 256 + threadIdx.x;
    if (i >= E) return;
    int s = ei[i], d = ei[E + i];
    int pos = atomicAdd(&g_cur[d], 1);
    g_srcs[pos] = s;
}

// ---------------- weight transpose + tf32 hi/lo split ----------------
__global__ void wprep_k(const float* __restrict__ p1, const float* __restrict__ l1,
                        const float* __restrict__ r1, const float* __restrict__ p2,
                        const float* __restrict__ l2, const float* __restrict__ r2)
{
    const float* w; float* th; float* tl; int K, N;
    switch (blockIdx.y) {
        case 0: w = p1; th = g_WtP1h; tl = g_WtP1l; K = 64;  N = 64;  break;
        case 1: w = l1; th = g_WtL1h; tl = g_WtL1l; K = 64;  N = 256; break;
        case 2: w = r1; th = g_WtR1h; tl = g_WtR1l; K = 64;  N = 256; break;
        case 3: w = p2; th = g_WtP2h; tl = g_WtP2l; K = 256; N = 256; break;
        case 4: w = l2; th = g_WtL2h; tl = g_WtL2l; K = 256; N = 128; break;
        default: w = r2; th = g_WtR2h; tl = g_WtR2l; K = 256; N = 128; break;
    }
    int i = blockIdx.x * 256 + threadIdx.x;
    if (i >= K * N) return;
    int k = i / N, n = i % N;
    float v = w[i];
    float hi = tf32_rna(v);
    th[(size_t)n * K + k] = hi;
    tl[(size_t)n * K + k] = tf32_rna(v - hi);
}

// ---------------- mma.sync tf32 GEMM body ----------------
// D[M,N] = A1[M,K1]@W1 (+ A2[M,K2]@W2) + bias; W given transposed [N][K], hi+lo.
// Block: 256 thr, 64 rows x full N. mma roles: mma-m = cols(N), mma-n = rows(M).
// EPI=0: row-L2-normalize + relu -> outf.  EPI=1: EP half2(e, e*v) -> outh.
template <int N, int K1, int K2, int WARPS_R, int WARPS_C, int EPI>
__device__ __forceinline__ void mm_body(
    const float* __restrict__ A1,
    const float* __restrict__ Bh1, const float* __restrict__ Bl1,
    const float* __restrict__ A2,
    const float* __restrict__ Bh2, const float* __restrict__ Bl2,
    const float* __restrict__ bias, const float* __restrict__ tv,
    float* __restrict__ outf, __half2* __restrict__ outh, int M)
{
    constexpr int WR = 64 / (8 * WARPS_R);   // row (mma-n8) tiles per warp
    constexpr int WC = N / (16 * WARPS_C);   // col (mma-m16) tiles per warp
    constexpr int LD = 36;                   // smem k-stride (floats), bank-safe
    constexpr int NS = N + 4;                // staging stride
    extern __shared__ float sm[];
    float* sbias = sm;                       // [N]
    float* stv   = sm + N;                   // [N]
    float* As    = sm + 2 * N;               // [64*LD]
    float* Wh    = As + 64 * LD;             // [N*LD]  (reused as Ds staging)
    float* Wl    = Wh + (size_t)N * LD;      // [N*LD]
    float* Ds    = Wh;                       // [64*NS] <= 2*N*LD

    int t = threadIdx.x, lane = t & 31, wid = t >> 5;
    int warp_c = wid % WARPS_C, warp_r = wid / WARPS_C;
    int rg = warp_r * WR * 8;
    int cg = warp_c * WC * 16;
    int m0 = blockIdx.x * 64;

    for (int i = t; i < N; i += 256) {
        sbias[i] = bias[i];
        if (EPI) stv[i] = tv[i];
    }

    float acc[WR][WC][4];
#pragma unroll
    for (int a = 0; a < WR; a++)
#pragma unroll
        for (int b = 0; b < WC; b++)
#pragma unroll
            for (int q = 0; q < 4; q++) acc[a][b][q] = 0.f;

#pragma unroll 1
    for (int phase = 0; phase < ((K2 > 0) ? 2 : 1); phase++) {
        const float* Ap = phase ? A2 : A1;
        const float* Bh = phase ? Bh2 : Bh1;
        const float* Bl = phase ? Bl2 : Bl1;
        const int K = phase ? K2 : K1;
#pragma unroll 1
        for (int kb = 0; kb < K; kb += 32) {
            __syncthreads();  // previous mma reads done before overwrite
            // activations: 64 x 32, tf32-round on store
#pragma unroll
            for (int s = t; s < 512; s += 256) {
                int row = s >> 3, k4 = (s & 7) * 4;
                int g = m0 + row;
                float4 v = make_float4(0.f, 0.f, 0.f, 0.f);
                if (g < M) v = *(const float4*)(Ap + (size_t)g * K + kb + k4);
                v.x = tf32_rna(v.x); v.y = tf32_rna(v.y);
                v.z = tf32_rna(v.z); v.w = tf32_rna(v.w);
                *(float4*)(As + row * LD + k4) = v;
            }
            // weights hi/lo: N x 32 (already tf32)
#pragma unroll
            for (int s = t; s < N * 8; s += 256) {
                int row = s >> 3, k4 = (s & 7) * 4;
                *(float4*)(Wh + row * LD + k4) =
                    *(const float4*)(Bh + (size_t)row * K + kb + k4);
                *(float4*)(Wl + row * LD + k4) =
                    *(const float4*)(Bl + (size_t)row * K + kb + k4);
            }
            __syncthreads();
#pragma unroll
            for (int ks = 0; ks < 4; ks++) {
                int k0 = ks * 8 + (lane & 3);
                uint32_t bf[WR][2];
#pragma unroll
                for (int nt = 0; nt < WR; nt++) {
                    int r = rg + nt * 8 + (lane >> 2);
                    bf[nt][0] = __float_as_uint(As[r * LD + k0]);
                    bf[nt][1] = __float_as_uint(As[r * LD + k0 + 4]);
                }
#pragma unroll
                for (int ct = 0; ct < WC; ct++) {
                    int nr = cg + ct * 16 + (lane >> 2);
                    uint32_t ah[4], al[4];
                    ah[0] = __float_as_uint(Wh[nr * LD + k0]);
                    ah[1] = __float_as_uint(Wh[(nr + 8) * LD + k0]);
                    ah[2] = __float_as_uint(Wh[nr * LD + k0 + 4]);
                    ah[3] = __float_as_uint(Wh[(nr + 8) * LD + k0 + 4]);
                    al[0] = __float_as_uint(Wl[nr * LD + k0]);
                    al[1] = __float_as_uint(Wl[(nr + 8) * LD + k0]);
                    al[2] = __float_as_uint(Wl[nr * LD + k0 + 4]);
                    al[3] = __float_as_uint(Wl[(nr + 8) * LD + k0 + 4]);
#pragma unroll
                    for (int nt = 0; nt < WR; nt++) {
                        mma8(acc[nt][ct], ah, bf[nt]);
                        mma8(acc[nt][ct], al, bf[nt]);
                    }
                }
            }
        }
    }

    __syncthreads();  // mma done everywhere before staging overwrites Wh
    // stage D^T fragments -> Ds[row_local][col], stride NS (conflict-free)
#pragma unroll
    for (int nt = 0; nt < WR; nt++)
#pragma unroll
        for (int ct = 0; ct < WC; ct++) {
            int rl = rg + nt * 8 + (lane & 3) * 2;
            int cl = cg + ct * 16 + (lane >> 2);
            Ds[rl * NS + cl]           = acc[nt][ct][0];
            Ds[(rl + 1) * NS + cl]     = acc[nt][ct][1];
            Ds[rl * NS + cl + 8]       = acc[nt][ct][2];
            Ds[(rl + 1) * NS + cl + 8] = acc[nt][ct][3];
        }
    __syncthreads();

    // stage 2: warp-per-row epilogue
    constexpr int J = N / 32;
#pragma unroll 1
    for (int r = wid; r < 64; r += 8) {
        int row = m0 + r;
        float v[J];
#pragma unroll
        for (int j = 0; j < J; j++)
            v[j] = Ds[r * NS + lane + 32 * j] + sbias[lane + 32 * j];
        if (EPI == 0) {
            float ssq = 0.f;
#pragma unroll
            for (int j = 0; j < J; j++) ssq += v[j] * v[j];
#pragma unroll
            for (int o = 16; o > 0; o >>= 1)
                ssq += __shfl_xor_sync(0xffffffffu, ssq, o);
            float inv = 1.0f / fmaxf(sqrtf(ssq), 1e-12f);
            if (row < M) {
#pragma unroll
                for (int j = 0; j < J; j++)
                    outf[(size_t)row * N + lane + 32 * j] = fmaxf(v[j] * inv, 0.f);
            }
        } else {
            if (row < M) {
#pragma unroll
                for (int j = 0; j < J; j++) {
                    float vv = fmaxf(v[j], 0.f);
                    float e = __expf(vv * stv[lane + 32 * j]);
                    outh[(size_t)row * N + lane + 32 * j] = __floats2half2_rn(e, e * vv);
                }
            }
        }
    }
}

// ---- GEMM wrapper kernels ----
__global__ __launch_bounds__(256) void mm_ep1_k(const float* __restrict__ x,
                                                const float* __restrict__ b,
                                                const float* __restrict__ tvv, int M)
{
    mm_body<64, 64, 0, 2, 4, 1>(x, g_WtP1h, g_WtP1l, nullptr, nullptr, nullptr,
                                b, tvv, nullptr, g_EP1, M);
}
__global__ __launch_bounds__(256) void mm_l1_k(const float* __restrict__ x,
                                               const float* __restrict__ bl, int M)
{
    mm_body<256, 64, 64, 1, 8, 0>(g_aggr1, g_WtL1h, g_WtL1l, x, g_WtR1h, g_WtR1l,
                                  bl, nullptr, g_buf1, nullptr, M);
}
__global__ __launch_bounds__(256) void mm_ep2_k(const float* __restrict__ b,
                                                const float* __restrict__ tvv, int M)
{
    mm_body<256, 256, 0, 1, 8, 1>(g_buf1, g_WtP2h, g_WtP2l, nullptr, nullptr, nullptr,
                                  b, tvv, nullptr, g_EP2, M);
}
__global__ __launch_bounds__(256) void mm_l2_k(const float* __restrict__ bl, int M)
{
    mm_body<128, 256, 256, 1, 8, 0>(g_aggr2, g_WtL2h, g_WtL2l, g_buf1, g_WtR2h, g_WtR2l,
                                    bl, nullptr, g_buf2, nullptr, M);
}

// ---------------- segment aggregation ----------------
__device__ __forceinline__ void acc_u4(uint4 u, float* den, float* num) {
    const __half2* h = (const __half2*)&u;
#pragma unroll
    for (int k = 0; k < 4; k++) {
        float2 f = __half22float2(h[k]);
        den[k] += f.x;
        num[k] += f.y;
    }
}

__global__ __launch_bounds__(256) void agg2_k(int M)  // C=256
{
    int w = (blockIdx.x * blockDim.x + threadIdx.x) >> 5;
    int lane = threadIdx.x & 31;
    if (w >= M) return;
    float den[8], num[8];
#pragma unroll
    for (int j = 0; j < 8; j++) { den[j] = 0.f; num[j] = 0.f; }
    int e0 = g_off[w], e1 = g_off[w + 1];
    int e = e0;
    for (; e + 1 < e1; e += 2) {
        int s0 = g_srcs[e], s1 = g_srcs[e + 1];
        const uint4* r0 = (const uint4*)(g_EP2 + (size_t)s0 * 256);
        const uint4* r1 = (const uint4*)(g_EP2 + (size_t)s1 * 256);
        uint4 a0 = __ldg(&r0[lane]), a1 = __ldg(&r0[lane + 32]);
        uint4 b0 = __ldg(&r1[lane]), b1 = __ldg(&r1[lane + 32]);
        acc_u4(a0, den, num);
        acc_u4(a1, den + 4, num + 4);
        acc_u4(b0, den, num);
        acc_u4(b1, den + 4, num + 4);
    }
    if (e < e1) {
        const uint4* r0 = (const uint4*)(g_EP2 + (size_t)g_srcs[e] * 256);
        uint4 a0 = __ldg(&r0[lane]), a1 = __ldg(&r0[lane + 32]);
        acc_u4(a0, den, num);
        acc_u4(a1, den + 4, num + 4);
    }
#pragma unroll
    for (int h = 0; h < 2; h++) {
        float4 o;
        o.x = num[4 * h + 0] / fmaxf(den[4 * h + 0], 1e-16f);
        o.y = num[4 * h + 1] / fmaxf(den[4 * h + 1], 1e-16f);
        o.z = num[4 * h + 2] / fmaxf(den[4 * h + 2], 1e-16f);
        o.w = num[4 * h + 3] / fmaxf(den[4 * h + 3], 1e-16f);
        *(float4*)(g_aggr2 + (size_t)w * 256 + 4 * (lane + 32 * h)) = o;
    }
}

__global__ __launch_bounds__(256) void agg1_k(int M)  // C=64
{
    int w = (blockIdx.x * blockDim.x + threadIdx.x) >> 5;
    int lane = threadIdx.x & 31;
    if (w >= M) return;
    float den[2] = {0.f, 0.f}, num[2] = {0.f, 0.f};
    int e0 = g_off[w], e1 = g_off[w + 1];
    int e = e0;
    for (; e + 1 < e1; e += 2) {
        int s0 = g_srcs[e], s1 = g_srcs[e + 1];
        uint2 a = __ldg((const uint2*)(g_EP1 + (size_t)s0 * 64) + lane);
        uint2 b = __ldg((const uint2*)(g_EP1 + (size_t)s1 * 64) + lane);
        float2 f0 = __half22float2(*(const __half2*)&a.x);
        float2 f1 = __half22float2(*(const __half2*)&a.y);
        float2 f2 = __half22float2(*(const __half2*)&b.x);
        float2 f3 = __half22float2(*(const __half2*)&b.y);
        den[0] += f0.x + f2.x; num[0] += f0.y + f2.y;
        den[1] += f1.x + f3.x; num[1] += f1.y + f3.y;
    }
    if (e < e1) {
        uint2 a = __ldg((const uint2*)(g_EP1 + (size_t)g_srcs[e] * 64) + lane);
        float2 f0 = __half22float2(*(const __half2*)&a.x);
        float2 f1 = __half22float2(*(const __half2*)&a.y);
        den[0] += f0.x; num[0] += f0.y;
        den[1] += f1.x; num[1] += f1.y;
    }
    float2 o;
    o.x = num[0] / fmaxf(den[0], 1e-16f);
    o.y = num[1] / fmaxf(den[1], 1e-16f);
    *(float2*)(g_aggr1 + (size_t)w * 64 + 2 * lane) = o;
}

// ---------------- MemPooling assignment + S^T @ h2 accumulation ----------------
__global__ __launch_bounds__(256) void pool_k(const float* __restrict__ k_mem,
                                              const float* __restrict__ w_conv,
                                              int M)
{
    __shared__ float kk[16 * 128];
    __shared__ float k2s[16];
    __shared__ float wc[4];
    int t = threadIdx.x;
    for (int i = t; i < 16 * 128; i += 256) kk[i] = k_mem[i];
    __syncthreads();
    if (t < 16) {
        float s = 0.f;
        for (int f = 0; f < 128; f++) { float kv = kk[t * 128 + f]; s += kv * kv; }
        k2s[t] = s;
    }
    if (t < 4) wc[t] = w_conv[t];
    __syncthreads();

    int lane = t & 31;
    int gw = blockIdx.x * 8 + (t >> 5);
    int step = gridDim.x * 8;

    float acc[4][4];
#pragma unroll
    for (int k = 0; k < 4; k++)
#pragma unroll
        for (int j = 0; j < 4; j++) acc[k][j] = 0.f;

    for (int n = gw; n < M; n += step) {
        float x4[4];
        const float* row = g_buf2 + (size_t)n * 128;
        float xx = 0.f;
#pragma unroll
        for (int j = 0; j < 4; j++) {
            x4[j] = row[lane + 32 * j];
            xx += x4[j] * x4[j];
        }
#pragma unroll
        for (int o = 16; o > 0; o >>= 1) xx += __shfl_xor_sync(0xffffffffu, xx, o);

        float p[16];
#pragma unroll
        for (int i = 0; i < 16; i++) {
            float s = 0.f;
#pragma unroll
            for (int j = 0; j < 4; j++) s += kk[i * 128 + lane + 32 * j] * x4[j];
            p[i] = s;
        }
#pragma unroll
        for (int i = 0; i < 16; i++)
#pragma unroll
            for (int o = 16; o > 0; o >>= 1)
                p[i] += __shfl_xor_sync(0xffffffffu, p[i], o);

        float dist[16];
#pragma unroll
        for (int i = 0; i < 16; i++) {
            float d2 = fmaxf(k2s[i] + xx - 2.0f * p[i], 0.0f);
            dist[i] = 1.0f / (1.0f + d2);
        }
        float mix[4] = {0.f, 0.f, 0.f, 0.f};
#pragma unroll
        for (int h = 0; h < 4; h++) {
            float sh = dist[4 * h] + dist[4 * h + 1] + dist[4 * h + 2] + dist[4 * h + 3];
            float invh = wc[h] / sh;
#pragma unroll
            for (int k = 0; k < 4; k++) mix[k] += invh * dist[4 * h + k];
        }
        float mmax = fmaxf(fmaxf(mix[0], mix[1]), fmaxf(mix[2], mix[3]));
        float e[4], se = 0.f;
#pragma unroll
        for (int k = 0; k < 4; k++) { e[k] = __expf(mix[k] - mmax); se += e[k]; }
        float invse = 1.0f / se;
#pragma unroll
        for (int k = 0; k < 4; k++) {
            float s = e[k] * invse;
#pragma unroll
            for (int j = 0; j < 4; j++) acc[k][j] += s * x4[j];
        }
    }
#pragma unroll
    for (int k = 0; k < 4; k++)
#pragma unroll
        for (int j = 0; j < 4; j++)
            atomicAdd(&g_pool[k * 128 + lane + 32 * j], acc[k][j]);
}

// ---------------- head ----------------
__global__ __launch_bounds__(128) void final_k(const float* __restrict__ w_memlin,
                                               const float* __restrict__ b_memlin,
                                               const float* __restrict__ w_fx,
                                               const float* __restrict__ b_fx,
                                               const float* __restrict__ gamma,
                                               const float* __restrict__ beta,
                                               float* __restrict__ out)
{
    __shared__ float s_xp[512];
    __shared__ float s_g[128];
    __shared__ float s_y[64];
    __shared__ float s_mu, s_var;
    int t = threadIdx.x;
    for (int i = t; i < 512; i += 128) s_xp[i] = g_pool[i];
    __syncthreads();
    {
        float s = 0.f;
        for (int k = 0; k < 4; k++) {
            float pk = 0.f;
            for (int f = 0; f < 128; f++) pk += s_xp[k * 128 + f] * w_memlin[f * 128 + t];
            s += pk;
        }
        s_g[t] = 0.25f * s + b_memlin[t];
    }
    __syncthreads();
    if (t < 64) {
        float y = b_fx[t];
        for (int c = 0; c < 128; c++) y += s_g[c] * w_fx[c * 64 + t];
        s_y[t] = y;
    }
    __syncthreads();
    if (t == 0) {
        float mu = 0.f;
        for (int i = 0; i < 64; i++) mu += s_y[i];
        mu *= (1.0f / 64.0f);
        float var = 0.f;
        for (int i = 0; i < 64; i++) { float d = s_y[i] - mu; var += d * d; }
        var *= (1.0f / 64.0f);
        s_mu = mu;
        s_var = var;
    }
    __syncthreads();
    if (t < 64) {
        float yv = (s_y[t] - s_mu) * rsqrtf(s_var + 1e-5f) * gamma[t] + beta[t];
        out[t] = fmaxf(yv, 0.0f);
    }
}

// ---------------- launch ----------------
extern "C" void kernel_launch(void* const* d_in, const int* in_sizes, int n_in,
                              void* d_out, int out_size)
{
    const float* x        = (const float*)d_in[0];
    const int*   ei       = (const int*)d_in[1];
    const float* w_proj1  = (const float*)d_in[2];
    const float* b_proj1  = (const float*)d_in[3];
    const float* t1       = (const float*)d_in[4];
    const float* w_l1     = (const float*)d_in[5];
    const float* b_l1     = (const float*)d_in[6];
    const float* w_r1     = (const float*)d_in[7];
    const float* w_proj2  = (const float*)d_in[8];
    const float* b_proj2  = (const float*)d_in[9];
    const float* t2       = (const float*)d_in[10];
    const float* w_l2     = (const float*)d_in[11];
    const float* b_l2     = (const float*)d_in[12];
    const float* w_r2     = (const float*)d_in[13];
    const float* k_mem    = (const float*)d_in[14];
    const float* w_conv   = (const float*)d_in[15];
    const float* w_memlin = (const float*)d_in[16];
    const float* b_memlin = (const float*)d_in[17];
    const float* w_fx     = (const float*)d_in[18];
    const float* b_fx     = (const float*)d_in[19];
    const float* gamma    = (const float*)d_in[20];
    const float* beta     = (const float*)d_in[21];
    float* out = (float*)d_out;

    int M = in_sizes[0] / 64;   // 50000
    int E = in_sizes[1] / 2;    // 800000

    int mb = (M + 63) / 64;     // 782 row-tile blocks
    int wb = (M + 7) / 8;
    int nb = (M + 1023) / 1024;

    // smem bytes: (2N + 64*36 + 2*N*36) * 4
    const int SM64  = (128 + 2304 + 4608) * 4;    // 28160
    const int SM128 = (256 + 2304 + 9216) * 4;    // 47104
    const int SM256 = (512 + 2304 + 18432) * 4;   // 84992
    cudaFuncSetAttribute(mm_ep1_k, cudaFuncAttributeMaxDynamicSharedMemorySize, SM64);
    cudaFuncSetAttribute(mm_l1_k,  cudaFuncAttributeMaxDynamicSharedMemorySize, SM256);
    cudaFuncSetAttribute(mm_ep2_k, cudaFuncAttributeMaxDynamicSharedMemorySize, SM256);
    cudaFuncSetAttribute(mm_l2_k,  cudaFuncAttributeMaxDynamicSharedMemorySize, SM128);

    // CSR build + weight prep
    zero_k<<<(M + 255) / 256, 256>>>(M);
    count_k<<<(E + 255) / 256, 256>>>(ei, E);
    wprep_k<<<dim3(256, 6), 256>>>(w_proj1, w_l1, w_r1, w_proj2, w_l2, w_r2);
    scan1_k<<<nb, 1024>>>(M);
    scan2_k<<<1, 64>>>(nb);
    scan3_k<<<(M + 255) / 256, 256>>>(M);
    scatter_k<<<(E + 255) / 256, 256>>>(ei, E);

    // Layer 1
    mm_ep1_k<<<mb, 256, SM64>>>(x, b_proj1, t1, M);
    agg1_k<<<wb, 256>>>(M);
    mm_l1_k<<<mb, 256, SM256>>>(x, b_l1, M);

    // Layer 2
    mm_ep2_k<<<mb, 256, SM256>>>(b_proj2, t2, M);
    agg2_k<<<wb, 256>>>(M);
    mm_l2_k<<<mb, 256, SM128>>>(b_l2, M);

    // MemPooling + head
    pool_k<<<512, 256>>>(k_mem, w_conv, M);
    final_k<<<1, 128>>>(w_memlin, b_memlin, w_fx, b_fx, gamma, beta, out);
}

// round 14
// speedup vs baseline: 1.4203x; 1.4203x over previous
#include <cuda_runtime.h>
#include <cuda_fp16.h>
#include <cstdint>
#include <cstddef>

#define NN 50000
#define NE 800000

// ---------------- static scratch (no allocs allowed) ----------------
__device__ __half2 g_EP1[(size_t)NN * 64];    // [n][c] = (E,P) half2, c<64
__device__ float   g_aggr1[(size_t)NN * 64];
__device__ float   g_buf1[(size_t)NN * 256];  // h1 (normalized+relu, fused epilogue)
__device__ __half2 g_EP2[(size_t)NN * 256];   // [n][c] c<256
__device__ float   g_aggr2[(size_t)NN * 256];
__device__ float   g_buf2[(size_t)NN * 128];  // h2
__device__ int     g_counts[NN];
__device__ int     g_off[NN + 1];
__device__ int     g_cur[NN];
__device__ int     g_srcs[NE];
__device__ int     g_bsum[64];
__device__ int     g_boff[64];
__device__ float   g_pool[4 * 128];

// ---------------- f32x2 helpers (Blackwell packed fp32) ----------------
__device__ __forceinline__ unsigned long long dup2(float a) {
    unsigned long long r; unsigned int u = __float_as_uint(a);
    asm("mov.b64 %0, {%1, %1};" : "=l"(r) : "r"(u));
    return r;
}
__device__ __forceinline__ unsigned long long fma2(unsigned long long a,
                                                   unsigned long long b,
                                                   unsigned long long c) {
    unsigned long long d;
    asm("fma.rn.f32x2 %0, %1, %2, %3;" : "=l"(d) : "l"(a), "l"(b), "l"(c));
    return d;
}
__device__ __forceinline__ float2 unpk2(unsigned long long v) {
    unsigned int lo, hi;
    asm("mov.b64 {%0, %1}, %2;" : "=r"(lo), "=r"(hi) : "l"(v));
    return make_float2(__uint_as_float(lo), __uint_as_float(hi));
}

// ---------------- CSR build ----------------
__global__ void zero_k(int n) {
    int i = blockIdx.x * 256 + threadIdx.x;
    if (i < n) g_counts[i] = 0;
    if (i < 512) g_pool[i] = 0.0f;
}

__global__ void count_k(const int* __restrict__ ei, int E) {
    int i = blockIdx.x * 256 + threadIdx.x;
    if (i >= E) return;
    atomicAdd(&g_counts[ei[E + i]], 1);
}

__global__ void scan1_k(int n) {
    __shared__ int s[1024];
    int t = threadIdx.x;
    int i = blockIdx.x * 1024 + t;
    int v = (i < n) ? g_counts[i] : 0;
    s[t] = v;
    __syncthreads();
    for (int o = 1; o < 1024; o <<= 1) {
        int a = (t >= o) ? s[t - o] : 0;
        __syncthreads();
        s[t] += a;
        __syncthreads();
    }
    if (i < n) g_off[i + 1] = s[t];
    if (t == 1023) g_bsum[blockIdx.x] = s[1023];
}

__global__ void scan2_k(int nb) {
    __shared__ int s[64];
    int t = threadIdx.x;
    int v = (t < nb) ? g_bsum[t] : 0;
    s[t] = v;
    __syncthreads();
    for (int o = 1; o < 64; o <<= 1) {
        int a = (t >= o) ? s[t - o] : 0;
        __syncthreads();
        s[t] += a;
        __syncthreads();
    }
    if (t < nb) g_boff[t] = s[t] - v;
}

__global__ void scan3_k(int n) {
    int i = blockIdx.x * 256 + threadIdx.x;
    if (i >= n) return;
    int incl = g_off[i + 1] + g_boff[i >> 10];
    g_off[i + 1] = incl;
    if (i + 1 < n) g_cur[i + 1] = incl;
    if (i == 0) { g_off[0] = 0; g_cur[0] = 0; }
}

__global__ void scatter_k(const int* __restrict__ ei, int E) {
    int i = blockIdx.x * 256 + threadIdx.x;
    if (i >= E) return;
    int s = ei[i], d = ei[E + i];
    int pos = atomicAdd(&g_cur[d], 1);
    g_srcs[pos] = s;
}

// ---------------- full-N SIMT GEMM body, f32x2 inner loop (rebalanced) ----------------
// C[M,N] = A[M,K1]@W[K1,N] (+ A2[M,K2]@W2[K2,N]) + bias
// One block covers BM=64 rows x ALL N columns (N in {64,128,256}).
// 256 threads = 8 warps. Warp w owns rows 8w..8w+7 (A fragment = warp broadcast);
// lane owns column pairs 2*lane + 64*j (B fragment = consecutive u64 LDS).
// EPI=0: +bias (and if NORM: row-L2-normalize + relu, fused).
// EPI=1: v=relu(acc+bias); write fp16 EP pairs half2(e, e*v), e=exp(v*t).
template <int EPI, int K1, int K2, int N, bool HAS2, bool NORM>
__device__ __forceinline__ void gemm_body(
    const float* __restrict__ A, const float* __restrict__ W,
    const float* __restrict__ A2, const float* __restrict__ W2,
    const float* __restrict__ bias, const float* __restrict__ tv,
    float* __restrict__ outf, __half2* __restrict__ outh, int M)
{
    constexpr int JP = N / 64;           // column-pair groups per thread
    __shared__ float As[16][64];
    __shared__ float Bs[16][N];
    int t = threadIdx.x;
    int m0 = blockIdx.x * 64;
    int lane = t & 31, wid = t >> 5;
    int lm = t >> 2, lk4 = (t & 3) * 4;  // A-tile load map
    int bk = t >> 4, bn4 = (t & 15) * 4; // B-tile load map

    unsigned long long acc[8][JP];
#pragma unroll
    for (int r = 0; r < 8; r++)
#pragma unroll
        for (int j = 0; j < JP; j++) acc[r][j] = 0ull;

#pragma unroll 1
    for (int phase = 0; phase < (HAS2 ? 2 : 1); ++phase) {
        const float* Ap = phase ? A2 : A;
        const float* Wp = phase ? W2 : W;
        const int Kp = phase ? K2 : K1;
        const int nt = Kp / 16;
#pragma unroll 1
        for (int kt = 0; kt < nt; ++kt) {
            int kb = kt * 16;
            float4 av4 = make_float4(0.f, 0.f, 0.f, 0.f);
            int arow = m0 + lm;
            if (arow < M) av4 = *(const float4*)(Ap + (size_t)arow * Kp + kb + lk4);
            float4 bv4[N / 64];
#pragma unroll
            for (int c = 0; c < N / 64; c++)
                bv4[c] = *(const float4*)(Wp + (size_t)(kb + bk) * N + bn4 + 64 * c);
            __syncthreads();  // previous compute done before smem overwrite
            As[lk4 + 0][lm] = av4.x;
            As[lk4 + 1][lm] = av4.y;
            As[lk4 + 2][lm] = av4.z;
            As[lk4 + 3][lm] = av4.w;
#pragma unroll
            for (int c = 0; c < N / 64; c++)
                *(float4*)&Bs[bk][bn4 + 64 * c] = bv4[c];
            __syncthreads();
#pragma unroll
            for (int k = 0; k < 16; k++) {
                // A fragment: this warp's 8 rows (broadcast across lanes)
                float4 a0 = *(const float4*)&As[k][8 * wid];
                float4 a1 = *(const float4*)&As[k][8 * wid + 4];
                // B fragment: column pairs
                unsigned long long b[JP];
#pragma unroll
                for (int j = 0; j < JP; j++)
                    b[j] = *(const unsigned long long*)&Bs[k][2 * lane + 64 * j];
                unsigned long long ar[8];
                ar[0] = dup2(a0.x); ar[1] = dup2(a0.y);
                ar[2] = dup2(a0.z); ar[3] = dup2(a0.w);
                ar[4] = dup2(a1.x); ar[5] = dup2(a1.y);
                ar[6] = dup2(a1.z); ar[7] = dup2(a1.w);
#pragma unroll
                for (int r = 0; r < 8; r++)
#pragma unroll
                    for (int j = 0; j < JP; j++)
                        acc[r][j] = fma2(ar[r], b[j], acc[r][j]);
            }
        }
    }

    // per-thread column params
    float2 bias2[JP], tv2[JP];
#pragma unroll
    for (int j = 0; j < JP; j++) {
        bias2[j] = *(const float2*)(bias + 2 * lane + 64 * j);
        if (EPI) tv2[j] = *(const float2*)(tv + 2 * lane + 64 * j);
    }

#pragma unroll
    for (int r = 0; r < 8; r++) {
        int row = m0 + 8 * wid + r;
        float v[JP][2];
#pragma unroll
        for (int j = 0; j < JP; j++) {
            float2 c = unpk2(acc[r][j]);
            v[j][0] = c.x + bias2[j].x;
            v[j][1] = c.y + bias2[j].y;
        }
        if (EPI == 0) {
            float inv = 1.0f;
            if (NORM) {
                float ssq = 0.f;
#pragma unroll
                for (int j = 0; j < JP; j++) ssq += v[j][0] * v[j][0] + v[j][1] * v[j][1];
#pragma unroll
                for (int o = 16; o > 0; o >>= 1)
                    ssq += __shfl_xor_sync(0xffffffffu, ssq, o);
                inv = 1.0f / fmaxf(sqrtf(ssq), 1e-12f);
            }
            if (row < M) {
#pragma unroll
                for (int j = 0; j < JP; j++) {
                    float2 o;
                    if (NORM) {
                        o.x = fmaxf(v[j][0] * inv, 0.0f);
                        o.y = fmaxf(v[j][1] * inv, 0.0f);
                    } else {
                        o = make_float2(v[j][0], v[j][1]);
                    }
                    *(float2*)(outf + (size_t)row * N + 2 * lane + 64 * j) = o;
                }
            }
        } else {
            if (row < M) {
#pragma unroll
                for (int j = 0; j < JP; j++) {
                    float v0 = fmaxf(v[j][0], 0.0f);
                    float v1 = fmaxf(v[j][1], 0.0f);
                    float e0 = __expf(v0 * tv2[j].x);
                    float e1 = __expf(v1 * tv2[j].y);
                    __half2 hp[2];
                    hp[0] = __floats2half2_rn(e0, e0 * v0);
                    hp[1] = __floats2half2_rn(e1, e1 * v1);
                    *(uint2*)(outh + (size_t)row * N + 2 * lane + 64 * j) =
                        *(const uint2*)hp;
                }
            }
        }
    }
}

// ---- GEMM wrapper kernels ----
__global__ __launch_bounds__(256) void gemm_ep1_k(
    const float* __restrict__ x, const float* __restrict__ w,
    const float* __restrict__ b, const float* __restrict__ tvv, int M)
{
    gemm_body<1, 64, 0, 64, false, false>(x, w, nullptr, nullptr, b, tvv,
                                          nullptr, g_EP1, M);
}
__global__ __launch_bounds__(256) void gemm_l1_k(
    const float* __restrict__ x, const float* __restrict__ wl,
    const float* __restrict__ bl, const float* __restrict__ wr, int M)
{
    gemm_body<0, 64, 64, 256, true, true>(g_aggr1, wl, x, wr, bl, nullptr,
                                          g_buf1, nullptr, M);
}
__global__ __launch_bounds__(256) void gemm_ep2_k(
    const float* __restrict__ w, const float* __restrict__ b,
    const float* __restrict__ tvv, int M)
{
    gemm_body<1, 256, 0, 256, false, false>(g_buf1, w, nullptr, nullptr, b, tvv,
                                            nullptr, g_EP2, M);
}
__global__ __launch_bounds__(256) void gemm_l2_k(
    const float* __restrict__ wl, const float* __restrict__ bl,
    const float* __restrict__ wr, int M)
{
    gemm_body<0, 256, 256, 128, true, true>(g_aggr2, wl, g_buf1, wr, bl, nullptr,
                                            g_buf2, nullptr, M);
}

// ---------------- segment aggregation: out = sum(P)/max(sum(E),1e-16) ----------------
__device__ __forceinline__ void acc_u4(uint4 u, float* den, float* num) {
    const __half2* h = (const __half2*)&u;
#pragma unroll
    for (int k = 0; k < 4; k++) {
        float2 f = __half22float2(h[k]);
        den[k] += f.x;
        num[k] += f.y;
    }
}

__global__ __launch_bounds__(256) void agg2_k(int M)  // C=256
{
    int w = (blockIdx.x * blockDim.x + threadIdx.x) >> 5;
    int lane = threadIdx.x & 31;
    if (w >= M) return;
    float den[8], num[8];
#pragma unroll
    for (int j = 0; j < 8; j++) { den[j] = 0.f; num[j] = 0.f; }
    int e0 = g_off[w], e1 = g_off[w + 1];
    int e = e0;
    for (; e + 1 < e1; e += 2) {
        int s0 = g_srcs[e], s1 = g_srcs[e + 1];
        const uint4* r0 = (const uint4*)(g_EP2 + (size_t)s0 * 256);
        const uint4* r1 = (const uint4*)(g_EP2 + (size_t)s1 * 256);
        uint4 a0 = __ldg(&r0[lane]), a1 = __ldg(&r0[lane + 32]);
        uint4 b0 = __ldg(&r1[lane]), b1 = __ldg(&r1[lane + 32]);
        acc_u4(a0, den, num);
        acc_u4(a1, den + 4, num + 4);
        acc_u4(b0, den, num);
        acc_u4(b1, den + 4, num + 4);
    }
    if (e < e1) {
        const uint4* r0 = (const uint4*)(g_EP2 + (size_t)g_srcs[e] * 256);
        uint4 a0 = __ldg(&r0[lane]), a1 = __ldg(&r0[lane + 32]);
        acc_u4(a0, den, num);
        acc_u4(a1, den + 4, num + 4);
    }
#pragma unroll
    for (int h = 0; h < 2; h++) {
        float4 o;
        o.x = num[4 * h + 0] / fmaxf(den[4 * h + 0], 1e-16f);
        o.y = num[4 * h + 1] / fmaxf(den[4 * h + 1], 1e-16f);
        o.z = num[4 * h + 2] / fmaxf(den[4 * h + 2], 1e-16f);
        o.w = num[4 * h + 3] / fmaxf(den[4 * h + 3], 1e-16f);
        *(float4*)(g_aggr2 + (size_t)w * 256 + 4 * (lane + 32 * h)) = o;
    }
}

__global__ __launch_bounds__(256) void agg1_k(int M)  // C=64
{
    int w = (blockIdx.x * blockDim.x + threadIdx.x) >> 5;
    int lane = threadIdx.x & 31;
    if (w >= M) return;
    float den[2] = {0.f, 0.f}, num[2] = {0.f, 0.f};
    int e0 = g_off[w], e1 = g_off[w + 1];
    int e = e0;
    for (; e + 1 < e1; e += 2) {
        int s0 = g_srcs[e], s1 = g_srcs[e + 1];
        uint2 a = __ldg((const uint2*)(g_EP1 + (size_t)s0 * 64) + lane);
        uint2 b = __ldg((const uint2*)(g_EP1 + (size_t)s1 * 64) + lane);
        float2 f0 = __half22float2(*(const __half2*)&a.x);
        float2 f1 = __half22float2(*(const __half2*)&a.y);
        float2 f2 = __half22float2(*(const __half2*)&b.x);
        float2 f3 = __half22float2(*(const __half2*)&b.y);
        den[0] += f0.x + f2.x; num[0] += f0.y + f2.y;
        den[1] += f1.x + f3.x; num[1] += f1.y + f3.y;
    }
    if (e < e1) {
        uint2 a = __ldg((const uint2*)(g_EP1 + (size_t)g_srcs[e] * 64) + lane);
        float2 f0 = __half22float2(*(const __half2*)&a.x);
        float2 f1 = __half22float2(*(const __half2*)&a.y);
        den[0] += f0.x; num[0] += f0.y;
        den[1] += f1.x; num[1] += f1.y;
    }
    float2 o;
    o.x = num[0] / fmaxf(den[0], 1e-16f);
    o.y = num[1] / fmaxf(den[1], 1e-16f);
    *(float2*)(g_aggr1 + (size_t)w * 64 + 2 * lane) = o;
}

// ---------------- MemPooling assignment + S^T @ h2 accumulation ----------------
__global__ __launch_bounds__(256) void pool_k(const float* __restrict__ k_mem,
                                              const float* __restrict__ w_conv,
                                              int M)
{
    __shared__ float kk[16 * 128];
    __shared__ float k2s[16];
    __shared__ float wc[4];
    int t = threadIdx.x;
    for (int i = t; i < 16 * 128; i += 256) kk[i] = k_mem[i];
    __syncthreads();
    if (t < 16) {
        float s = 0.f;
        for (int f = 0; f < 128; f++) { float kv = kk[t * 128 + f]; s += kv * kv; }
        k2s[t] = s;
    }
    if (t < 4) wc[t] = w_conv[t];
    __syncthreads();

    int lane = t & 31;
    int gw = blockIdx.x * 8 + (t >> 5);
    int step = gridDim.x * 8;

    float acc[4][4];
#pragma unroll
    for (int k = 0; k < 4; k++)
#pragma unroll
        for (int j = 0; j < 4; j++) acc[k][j] = 0.f;

    for (int n = gw; n < M; n += step) {
        float x4[4];
        const float* row = g_buf2 + (size_t)n * 128;
        float xx = 0.f;
#pragma unroll
        for (int j = 0; j < 4; j++) {
            x4[j] = row[lane + 32 * j];
            xx += x4[j] * x4[j];
        }
#pragma unroll
        for (int o = 16; o > 0; o >>= 1) xx += __shfl_xor_sync(0xffffffffu, xx, o);

        float p[16];
#pragma unroll
        for (int i = 0; i < 16; i++) {
            float s = 0.f;
#pragma unroll
            for (int j = 0; j < 4; j++) s += kk[i * 128 + lane + 32 * j] * x4[j];
            p[i] = s;
        }
#pragma unroll
        for (int i = 0; i < 16; i++)
#pragma unroll
            for (int o = 16; o > 0; o >>= 1)
                p[i] += __shfl_xor_sync(0xffffffffu, p[i], o);

        float dist[16];
#pragma unroll
        for (int i = 0; i < 16; i++) {
            float d2 = fmaxf(k2s[i] + xx - 2.0f * p[i], 0.0f);
            dist[i] = 1.0f / (1.0f + d2);
        }
        float mix[4] = {0.f, 0.f, 0.f, 0.f};
#pragma unroll
        for (int h = 0; h < 4; h++) {
            float sh = dist[4 * h] + dist[4 * h + 1] + dist[4 * h + 2] + dist[4 * h + 3];
            float invh = wc[h] / sh;
#pragma unroll
            for (int k = 0; k < 4; k++) mix[k] += invh * dist[4 * h + k];
        }
        float mmax = fmaxf(fmaxf(mix[0], mix[1]), fmaxf(mix[2], mix[3]));
        float e[4], se = 0.f;
#pragma unroll
        for (int k = 0; k < 4; k++) { e[k] = __expf(mix[k] - mmax); se += e[k]; }
        float invse = 1.0f / se;
#pragma unroll
        for (int k = 0; k < 4; k++) {
            float s = e[k] * invse;
#pragma unroll
            for (int j = 0; j < 4; j++) acc[k][j] += s * x4[j];
        }
    }
#pragma unroll
    for (int k = 0; k < 4; k++)
#pragma unroll
        for (int j = 0; j < 4; j++)
            atomicAdd(&g_pool[k * 128 + lane + 32 * j], acc[k][j]);
}

// ---------------- head: memlin + mean pool + fx + LayerNorm + relu ----------------
__global__ __launch_bounds__(128) void final_k(const float* __restrict__ w_memlin,
                                               const float* __restrict__ b_memlin,
                                               const float* __restrict__ w_fx,
                                               const float* __restrict__ b_fx,
                                               const float* __restrict__ gamma,
                                               const float* __restrict__ beta,
                                               float* __restrict__ out)
{
    __shared__ float s_xp[512];
    __shared__ float s_g[128];
    __shared__ float s_y[64];
    __shared__ float s_mu, s_var;
    int t = threadIdx.x;
    for (int i = t; i < 512; i += 128) s_xp[i] = g_pool[i];
    __syncthreads();
    {
        float s = 0.f;
        for (int k = 0; k < 4; k++) {
            float pk = 0.f;
            for (int f = 0; f < 128; f++) pk += s_xp[k * 128 + f] * w_memlin[f * 128 + t];
            s += pk;
        }
        s_g[t] = 0.25f * s + b_memlin[t];
    }
    __syncthreads();
    if (t < 64) {
        float y = b_fx[t];
        for (int c = 0; c < 128; c++) y += s_g[c] * w_fx[c * 64 + t];
        s_y[t] = y;
    }
    __syncthreads();
    if (t == 0) {
        float mu = 0.f;
        for (int i = 0; i < 64; i++) mu += s_y[i];
        mu *= (1.0f / 64.0f);
        float var = 0.f;
        for (int i = 0; i < 64; i++) { float d = s_y[i] - mu; var += d * d; }
        var *= (1.0f / 64.0f);
        s_mu = mu;
        s_var = var;
    }
    __syncthreads();
    if (t < 64) {
        float yv = (s_y[t] - s_mu) * rsqrtf(s_var + 1e-5f) * gamma[t] + beta[t];
        out[t] = fmaxf(yv, 0.0f);
    }
}

// ---------------- launch ----------------
extern "C" void kernel_launch(void* const* d_in, const int* in_sizes, int n_in,
                              void* d_out, int out_size)
{
    const float* x        = (const float*)d_in[0];
    const int*   ei       = (const int*)d_in[1];
    const float* w_proj1  = (const float*)d_in[2];
    const float* b_proj1  = (const float*)d_in[3];
    const float* t1       = (const float*)d_in[4];
    const float* w_l1     = (const float*)d_in[5];
    const float* b_l1     = (const float*)d_in[6];
    const float* w_r1     = (const float*)d_in[7];
    const float* w_proj2  = (const float*)d_in[8];
    const float* b_proj2  = (const float*)d_in[9];
    const float* t2       = (const float*)d_in[10];
    const float* w_l2     = (const float*)d_in[11];
    const float* b_l2     = (const float*)d_in[12];
    const float* w_r2     = (const float*)d_in[13];
    const float* k_mem    = (const float*)d_in[14];
    const float* w_conv   = (const float*)d_in[15];
    const float* w_memlin = (const float*)d_in[16];
    const float* b_memlin = (const float*)d_in[17];
    const float* w_fx     = (const float*)d_in[18];
    const float* b_fx     = (const float*)d_in[19];
    const float* gamma    = (const float*)d_in[20];
    const float* beta     = (const float*)d_in[21];
    float* out = (float*)d_out;

    int M = in_sizes[0] / 64;   // 50000
    int E = in_sizes[1] / 2;    // 800000

    int mb = (M + 63) / 64;     // row-tile blocks (782)
    int wb = (M + 7) / 8;       // warp-per-row blocks (256 thr = 8 warps)
    int nb = (M + 1023) / 1024; // scan chunks (49)

    // CSR build + zero pool accumulator
    zero_k<<<(M + 255) / 256, 256>>>(M);
    count_k<<<(E + 255) / 256, 256>>>(ei, E);
    scan1_k<<<nb, 1024>>>(M);
    scan2_k<<<1, 64>>>(nb);
    scan3_k<<<(M + 255) / 256, 256>>>(M);
    scatter_k<<<(E + 255) / 256, 256>>>(ei, E);

    // Layer 1
    gemm_ep1_k<<<mb, 256>>>(x, w_proj1, b_proj1, t1, M);
    agg1_k<<<wb, 256>>>(M);
    gemm_l1_k<<<mb, 256>>>(x, w_l1, b_l1, w_r1, M);   // fused norm+relu

    // Layer 2
    gemm_ep2_k<<<mb, 256>>>(w_proj2, b_proj2, t2, M);
    agg2_k<<<wb, 256>>>(M);
    gemm_l2_k<<<mb, 256>>>(w_l2, b_l2, w_r2, M);      // fused norm+relu

    // MemPooling + head
    pool_k<<<512, 256>>>(k_mem, w_conv, M);
    final_k<<<1, 128>>>(w_memlin, b_memlin, w_fx, b_fx, gamma, beta, out);
}